// round 15
// baseline (speedup 1.0000x reference)
#include <cuda_runtime.h>
#include <cuda_bf16.h>
#include <math_constants.h>

// Problem constants
#define B_  2
#define S_  2048
#define D_  1024
#define H_  16
#define HD_ 64
#define BH_ (B_ * H_)          // 32
#define MS_ (B_ * S_)          // 4096
#define CTX_ELEMS  (4194304LL)

// NOTE (R13): harness compiles at compute_103 (no 'a'); tcgen05 unavailable.

// Scratch (device globals, 16B-aligned). NEVER pass these as kernel args from
// host (host shadow + GB300 ATS serves zeros) — resolve inside kernels.
__device__ __align__(16) __nv_bfloat16 g_qh[BH_ * S_ * HD_];
__device__ __align__(16) __nv_bfloat16 g_ql[BH_ * S_ * HD_];
__device__ __align__(16) __nv_bfloat16 g_kh[BH_ * S_ * HD_];
__device__ __align__(16) __nv_bfloat16 g_kl[BH_ * S_ * HD_];
__device__ __align__(16) __nv_bfloat16 g_vh[BH_ * S_ * HD_];
__device__ __align__(16) __nv_bfloat16 g_vl[BH_ * S_ * HD_];
__device__ __align__(16) __nv_bfloat16 g_ah[MS_ * D_];      // A operand: x, then ctx
__device__ __align__(16) __nv_bfloat16 g_al[MS_ * D_];
__device__ __align__(16) __nv_bfloat16 g_w1h[D_ * 3 * D_];
__device__ __align__(16) __nv_bfloat16 g_w1l[D_ * 3 * D_];
__device__ __align__(16) __nv_bfloat16 g_w2h[D_ * D_];
__device__ __align__(16) __nv_bfloat16 g_w2l[D_ * D_];

// ---------------------------------------------------------------------------
__device__ __forceinline__ unsigned su32(const void* p) {
    return (unsigned)__cvta_generic_to_shared(p);
}

#define LDSM4(r0, r1, r2, r3, addr)                                          \
    asm volatile("ldmatrix.sync.aligned.m8n8.x4.shared.b16 {%0,%1,%2,%3},[%4];" \
                 : "=r"(r0), "=r"(r1), "=r"(r2), "=r"(r3) : "r"(addr))

#define LDSM2(r0, r1, addr)                                                  \
    asm volatile("ldmatrix.sync.aligned.m8n8.x2.shared.b16 {%0,%1},[%2];"    \
                 : "=r"(r0), "=r"(r1) : "r"(addr))

#define LDSM2T(r0, r1, addr)                                                 \
    asm volatile("ldmatrix.sync.aligned.m8n8.x2.trans.shared.b16 {%0,%1},[%2];" \
                 : "=r"(r0), "=r"(r1) : "r"(addr))

#define MMA16816(d, a, b)                                                    \
    asm volatile("mma.sync.aligned.m16n8k16.row.col.f32.bf16.bf16.f32 "      \
                 "{%0,%1,%2,%3},{%4,%5,%6,%7},{%8,%9},{%0,%1,%2,%3};"        \
                 : "+f"(d[0]), "+f"(d[1]), "+f"(d[2]), "+f"(d[3])            \
                 : "r"(a[0]), "r"(a[1]), "r"(a[2]), "r"(a[3]),               \
                   "r"(b[0]), "r"(b[1]))

#define CP_ASYNC16(saddr, gptr)                                              \
    asm volatile("cp.async.cg.shared.global [%0], [%1], 16;"                 \
                 :: "r"(saddr), "l"(gptr))
#define CP_COMMIT()  asm volatile("cp.async.commit_group;")
#define CP_WAIT(N)   asm volatile("cp.async.wait_group %0;" :: "n"(N))

__device__ __forceinline__ void f2bf2(float v, __nv_bfloat16& h, __nv_bfloat16& l) {
    h = __float2bfloat16_rn(v);
    l = __float2bfloat16_rn(v - __bfloat162float(h));
}

__device__ __forceinline__ unsigned packbf(__nv_bfloat16 a, __nv_bfloat16 b) {
    __nv_bfloat162 t = __halves2bfloat162(a, b);
    return *(unsigned*)&t;
}

// pv smem geometry
#define TSTR 72
#define TPLANE (64 * TSTR)
#define TPLANE_B (TPLANE * 2)
#define KSTAGE (2 * TPLANE)

// ---------------------------------------------------------------------------
// convert: fp32 -> bf16 hi/lo planes. which: 0=g_ah/g_al, 1=W_qkv, 2=W_out
// ---------------------------------------------------------------------------
__global__ void convert_kernel(const float* __restrict__ src, int n4, int which)
{
    __nv_bfloat162* dh;
    __nv_bfloat162* dl;
    if (which == 0)      { dh = (__nv_bfloat162*)g_ah;  dl = (__nv_bfloat162*)g_al;  }
    else if (which == 1) { dh = (__nv_bfloat162*)g_w1h; dl = (__nv_bfloat162*)g_w1l; }
    else                 { dh = (__nv_bfloat162*)g_w2h; dl = (__nv_bfloat162*)g_w2l; }

    int stride = gridDim.x * blockDim.x;
    for (int i = blockIdx.x * blockDim.x + threadIdx.x; i < n4; i += stride) {
        float4 v = *(const float4*)(src + 4 * (size_t)i);
        __nv_bfloat16 h0, l0, h1, l1, h2, l2, h3, l3;
        f2bf2(v.x, h0, l0); f2bf2(v.y, h1, l1);
        f2bf2(v.z, h2, l2); f2bf2(v.w, h3, l3);
        dh[2 * i]     = __halves2bfloat162(h0, h1);
        dh[2 * i + 1] = __halves2bfloat162(h2, h3);
        dl[2 * i]     = __halves2bfloat162(l0, l1);
        dl[2 * i + 1] = __halves2bfloat162(l2, l3);
    }
}

// ---------------------------------------------------------------------------
// tc_gemm_bf16: 128x64 block tile (2 blocks/SM), warp tile 32x32, BK=32,
// cp.async double-buffered, hoisted staging. mode 1: scatter q/k/v hi/lo;
// mode 2: C = A@W + bias.
// ---------------------------------------------------------------------------
#define GA_STG (2 * 128 * 40)        // elems per A stage (hi+lo)
#define GB_STG (2 * 32 * 72)         // elems per B stage (hi+lo), 64-col tile
#define GA_LO  (128 * 40 * 2)        // bytes hi->lo within A stage
#define GB_LO  (32 * 72 * 2)         // bytes hi->lo within B stage

__global__ __launch_bounds__(256, 2)
void tc_gemm_bf16(const float* __restrict__ bias, float* __restrict__ C,
                  int N, int mode)
{
    extern __shared__ __nv_bfloat16 gsm[];
    __nv_bfloat16* As = gsm;                    // 2 stages
    __nv_bfloat16* Bs = gsm + 2 * GA_STG;

    const __nv_bfloat16* Wh = (mode == 1) ? g_w1h : g_w2h;
    const __nv_bfloat16* Wl = (mode == 1) ? g_w1l : g_w2l;
    const int K = 1024;

    const int tid  = threadIdx.x;
    const int lane = tid & 31;
    const int w    = tid >> 5;
    const int wm   = w >> 1;          // 0..3 -> 32 rows each
    const int wn   = w & 1;           // 0..1 -> 32 cols each
    const int m0   = blockIdx.y * 128;
    const int n0   = blockIdx.x * 64;

    float acc[2][4][4];
#pragma unroll
    for (int i = 0; i < 2; i++)
#pragma unroll
        for (int j = 0; j < 4; j++)
#pragma unroll
            for (int r = 0; r < 4; r++) acc[i][j][r] = 0.f;

    // hoisted staging addressing
    // A: 1024 16B-chunks -> 4/thread;  B: 512 chunks -> 2/thread
    const __nv_bfloat16* srcA[4]; unsigned dstA[4];
    const __nv_bfloat16* srcB[2]; unsigned dstB[2];
#pragma unroll
    for (int u = 0; u < 4; u++) {
        int id = u * 256 + tid;
        int pl = id >> 9, wi = id & 511;
        int row = wi >> 2, c = wi & 3;
        srcA[u] = (pl ? g_al : g_ah) + (size_t)(m0 + row) * K + c * 8;
        dstA[u] = su32(As + pl * (128 * 40) + row * 40 + c * 8);
    }
#pragma unroll
    for (int u = 0; u < 2; u++) {
        int id = u * 256 + tid;
        int pl = id >> 8, wi = id & 255;
        int row = wi >> 3, c = wi & 7;
        srcB[u] = (pl ? Wl : Wh) + (size_t)row * N + n0 + c * 8;
        dstB[u] = su32(Bs + pl * (32 * 72) + row * 72 + c * 8);
    }
    const unsigned ASTG_B = GA_STG * 2;
    const unsigned BSTG_B = GB_STG * 2;

    auto stage = [&](int st, int k0) {
        unsigned ao = st ? ASTG_B : 0u;
        unsigned bo = st ? BSTG_B : 0u;
        size_t bstep = (size_t)k0 * N;
#pragma unroll
        for (int u = 0; u < 4; u++) CP_ASYNC16(dstA[u] + ao, srcA[u] + k0);
#pragma unroll
        for (int u = 0; u < 2; u++) CP_ASYNC16(dstB[u] + bo, srcB[u] + bstep);
        CP_COMMIT();
    };

    stage(0, 0);

    const unsigned aBase = su32(As + (wm * 32 + (lane & 15)) * 40 + (lane >> 4) * 8);
    const unsigned bBase = su32(Bs + (lane & 15) * 72 + wn * 32);

    for (int it = 0; it < 32; it++) {
        if (it + 1 < 32) { stage((it + 1) & 1, (it + 1) * 32); CP_WAIT(1); }
        else             { CP_WAIT(0); }
        __syncthreads();
        const unsigned aS = aBase + (it & 1) * ASTG_B;
        const unsigned bS = bBase + (it & 1) * BSTG_B;

#pragma unroll
        for (int ks = 0; ks < 32; ks += 16) {
            unsigned bh2[4][2], bl2[4][2];
#pragma unroll
            for (int j = 0; j < 4; j++) {
                unsigned ba = bS + (unsigned)(ks * 72 + j * 8) * 2;
                LDSM2T(bh2[j][0], bh2[j][1], ba);
                LDSM2T(bl2[j][0], bl2[j][1], ba + GB_LO);
            }
#pragma unroll
            for (int i = 0; i < 2; i++) {
                unsigned ah[4], al[4];
                unsigned aa = aS + (unsigned)(i * 16 * 40 + ks) * 2;
                LDSM4(ah[0], ah[1], ah[2], ah[3], aa);
                LDSM4(al[0], al[1], al[2], al[3], aa + GA_LO);
#pragma unroll
                for (int j = 0; j < 4; j++) {
                    MMA16816(acc[i][j], ah, bh2[j]);
                    MMA16816(acc[i][j], ah, bl2[j]);
                    MMA16816(acc[i][j], al, bh2[j]);
                }
            }
        }
        __syncthreads();
    }

    const int g = lane >> 2, tg = lane & 3;
    if (mode == 1) {
#pragma unroll
        for (int i = 0; i < 2; i++) {
            int mrow = m0 + wm * 32 + i * 16 + g;
            int b = mrow >> 11, s = mrow & (S_ - 1);
#pragma unroll
            for (int j = 0; j < 4; j++) {
                int c = n0 + wn * 32 + j * 8 + tg * 2;
                int sec = c >> 10;
                int within = c & 1023;
                int h = within >> 6, hd = within & 63;
                __nv_bfloat16 *oh, *ol;
                if (sec == 0)      { oh = g_qh; ol = g_ql; }
                else if (sec == 1) { oh = g_kh; ol = g_kl; }
                else               { oh = g_vh; ol = g_vl; }
                size_t base = ((size_t)(b * H_ + h) * S_ + s) * HD_ + hd;
                __nv_bfloat16 h0, l0, h1, l1;
                f2bf2(acc[i][j][0], h0, l0); f2bf2(acc[i][j][1], h1, l1);
                *(__nv_bfloat162*)(oh + base) = __halves2bfloat162(h0, h1);
                *(__nv_bfloat162*)(ol + base) = __halves2bfloat162(l0, l1);
                f2bf2(acc[i][j][2], h0, l0); f2bf2(acc[i][j][3], h1, l1);
                *(__nv_bfloat162*)(oh + base + 512) = __halves2bfloat162(h0, h1);
                *(__nv_bfloat162*)(ol + base + 512) = __halves2bfloat162(l0, l1);
            }
        }
    } else {
#pragma unroll
        for (int i = 0; i < 2; i++) {
            int mrow = m0 + wm * 32 + i * 16 + g;
#pragma unroll
            for (int j = 0; j < 4; j++) {
                int c = n0 + wn * 32 + j * 8 + tg * 2;
                float2 bv = *(const float2*)(bias + c);
                *(float2*)(C + (size_t)mrow * N + c) =
                    make_float2(acc[i][j][0] + bv.x, acc[i][j][1] + bv.y);
                *(float2*)(C + (size_t)(mrow + 8) * N + c) =
                    make_float2(acc[i][j][2] + bv.x, acc[i][j][3] + bv.y);
            }
        }
    }
}

// ---------------------------------------------------------------------------
// pv_fused: 128-q-row tiles, max-free softmax, hoisted K/V prefetch, fused
// normalize + zero-fill epilogue (R14, unchanged).
// ---------------------------------------------------------------------------
__global__ __launch_bounds__(256, 2)
void pv_fused(float* __restrict__ attnP)
{
    extern __shared__ __nv_bfloat16 psm[];
    __nv_bfloat16* Qs = psm;
    __nv_bfloat16* Kr = Qs + 2 * 128 * TSTR;
    __nv_bfloat16* Vr = Kr + 2 * KSTAGE;
    __shared__ float rlrow[128];

    const int qt   = 15 - blockIdx.x;
    const int bh   = blockIdx.y;
    const int tid  = threadIdx.x;
    const int lane = tid & 31;
    const int w    = tid >> 5;
    const int lr   = lane >> 2, lc = lane & 3;
    const int nkt  = 2 * qt + 2;

    const __nv_bfloat16* srcKV[8]; unsigned dstKV[8];
    {
        const size_t gb = (size_t)bh * S_ * HD_;
#pragma unroll
        for (int u = 0; u < 8; u++) {
            int id = u * 256 + tid;
            int pl = id >> 9, wi = id & 511;
            int row = wi >> 3, c8 = (wi & 7) * 8;
            srcKV[u] = (pl == 0 ? g_kh : pl == 1 ? g_kl : pl == 2 ? g_vh : g_vl)
                       + gb + row * HD_ + c8;
            dstKV[u] = su32(((pl < 2) ? Kr : Vr) + (pl & 1) * TPLANE + row * TSTR + c8);
        }
    }
    auto prefetch = [&](int kt) {
        unsigned so = (kt & 1) ? (unsigned)(KSTAGE * 2) : 0u;
        int go = kt * (64 * HD_);
#pragma unroll
        for (int u = 0; u < 8; u++) CP_ASYNC16(dstKV[u] + so, srcKV[u] + go);
        CP_COMMIT();
    };

    prefetch(0);

    {
        const size_t qoff = ((size_t)bh * S_ + qt * 128) * HD_;
#pragma unroll
        for (int u = 0; u < 4; u++) {
            int id = u * 256 + tid;
            int row = id >> 3, c8 = (id & 7) * 8;
            *(int4*)(Qs + row * TSTR + c8) =
                *(const int4*)(g_qh + qoff + row * HD_ + c8);
            *(int4*)(Qs + 128 * TSTR + row * TSTR + c8) =
                *(const int4*)(g_ql + qoff + row * HD_ + c8);
        }
    }
    __syncthreads();

    unsigned qh[4][4], ql[4][4];
#pragma unroll
    for (int ks = 0; ks < 4; ks++) {
        unsigned a = su32(Qs + (w * 16 + (lane & 15)) * TSTR + (lane >> 4) * 8 + ks * 16);
        LDSM4(qh[ks][0], qh[ks][1], qh[ks][2], qh[ks][3], a);
        LDSM4(ql[ks][0], ql[ks][1], ql[ks][2], ql[ks][3], a + 128 * TSTR * 2);
    }

    const int qbase = qt * 128 + w * 16;
    const int qg0 = qbase + lr;
    const int qg1 = qg0 + 8;
    const size_t arow0 = ((size_t)bh * S_ + qg0) * S_;
    const size_t arow1 = ((size_t)bh * S_ + qg1) * S_;

    float oacc[8][4];
#pragma unroll
    for (int j = 0; j < 8; j++)
#pragma unroll
        for (int r = 0; r < 4; r++) oacc[j][r] = 0.f;

    float lsum0 = 0.f, lsum1 = 0.f;

    for (int kt = 0; kt < nkt; kt++) {
        if (kt + 1 < nkt) { prefetch(kt + 1); CP_WAIT(1); }
        else              { CP_WAIT(0); }
        __syncthreads();

        if (64 * kt <= qbase + 15) {
            const __nv_bfloat16* Ks = Kr + (kt & 1) * KSTAGE;
            const __nv_bfloat16* Vs = Vr + (kt & 1) * KSTAGE;

#pragma unroll
            for (int hh = 0; hh < 2; hh++) {
                float sacc[4][4];
#pragma unroll
                for (int j = 0; j < 4; j++)
#pragma unroll
                    for (int r = 0; r < 4; r++) sacc[j][r] = 0.f;
#pragma unroll
                for (int ks = 0; ks < 4; ks++) {
#pragma unroll
                    for (int j = 0; j < 4; j++) {
                        unsigned addr = su32(Ks + (hh * 32 + j * 8 + (lane & 7)) * TSTR
                                             + ks * 16 + ((lane >> 3) & 1) * 8);
                        unsigned bhf[2], blf[2];
                        LDSM2(bhf[0], bhf[1], addr);
                        LDSM2(blf[0], blf[1], addr + TPLANE_B);
                        MMA16816(sacc[j], qh[ks], bhf);
                        MMA16816(sacc[j], qh[ks], blf);
                        MMA16816(sacc[j], ql[ks], bhf);
                    }
                }

                float p[4][4];
#pragma unroll
                for (int j = 0; j < 4; j++) {
                    int kg = kt * 64 + hh * 32 + j * 8 + lc * 2;
                    p[j][0] = (kg     <= qg0) ? __expf(sacc[j][0] * 0.125f) : 0.f;
                    p[j][1] = (kg + 1 <= qg0) ? __expf(sacc[j][1] * 0.125f) : 0.f;
                    p[j][2] = (kg     <= qg1) ? __expf(sacc[j][2] * 0.125f) : 0.f;
                    p[j][3] = (kg + 1 <= qg1) ? __expf(sacc[j][3] * 0.125f) : 0.f;
                    lsum0 += p[j][0] + p[j][1];
                    lsum1 += p[j][2] + p[j][3];
                    *(float2*)(attnP + arow0 + kg) = make_float2(p[j][0], p[j][1]);
                    *(float2*)(attnP + arow1 + kg) = make_float2(p[j][2], p[j][3]);
                }

#pragma unroll
                for (int g = 0; g < 2; g++) {
                    int j0 = 2 * g, j1 = 2 * g + 1;
                    __nv_bfloat16 h00, l00, h01, l01, h02, l02, h03, l03;
                    __nv_bfloat16 h10, l10, h11, l11, h12, l12, h13, l13;
                    f2bf2(p[j0][0], h00, l00); f2bf2(p[j0][1], h01, l01);
                    f2bf2(p[j0][2], h02, l02); f2bf2(p[j0][3], h03, l03);
                    f2bf2(p[j1][0], h10, l10); f2bf2(p[j1][1], h11, l11);
                    f2bf2(p[j1][2], h12, l12); f2bf2(p[j1][3], h13, l13);
                    unsigned aph[4] = { packbf(h00, h01), packbf(h02, h03),
                                        packbf(h10, h11), packbf(h12, h13) };
                    unsigned apl[4] = { packbf(l00, l01), packbf(l02, l03),
                                        packbf(l10, l11), packbf(l12, l13) };
#pragma unroll
                    for (int j2 = 0; j2 < 8; j2++) {
                        unsigned va = su32(Vs + (hh * 32 + g * 16 + (lane & 15)) * TSTR + j2 * 8);
                        unsigned bvh[2], bvl[2];
                        LDSM2T(bvh[0], bvh[1], va);
                        LDSM2T(bvl[0], bvl[1], va + TPLANE_B);
                        MMA16816(oacc[j2], aph, bvh);
                        MMA16816(oacc[j2], aph, bvl);
                        MMA16816(oacc[j2], apl, bvh);
                    }
                }
            }
        }
        __syncthreads();
    }

#pragma unroll
    for (int d = 1; d <= 2; d <<= 1) {
        lsum0 += __shfl_xor_sync(0xffffffffu, lsum0, d);
        lsum1 += __shfl_xor_sync(0xffffffffu, lsum1, d);
    }
    const float rl0 = 1.f / lsum0;
    const float rl1 = 1.f / lsum1;
    if (lc == 0) {
        rlrow[w * 16 + lr]     = rl0;
        rlrow[w * 16 + lr + 8] = rl1;
    }

    {
        const int b = bh >> 4, h = bh & 15;
        const size_t r0 = ((size_t)(b * S_ + qg0)) * D_ + h * HD_;
        const size_t r1 = ((size_t)(b * S_ + qg1)) * D_ + h * HD_;
#pragma unroll
        for (int j2 = 0; j2 < 8; j2++) {
            int cc = j2 * 8 + lc * 2;
            __nv_bfloat16 h0, l0, h1, l1;
            f2bf2(oacc[j2][0] * rl0, h0, l0); f2bf2(oacc[j2][1] * rl0, h1, l1);
            *(__nv_bfloat162*)(g_ah + r0 + cc) = __halves2bfloat162(h0, h1);
            *(__nv_bfloat162*)(g_al + r0 + cc) = __halves2bfloat162(l0, l1);
            f2bf2(oacc[j2][2] * rl1, h0, l0); f2bf2(oacc[j2][3] * rl1, h1, l1);
            *(__nv_bfloat162*)(g_ah + r1 + cc) = __halves2bfloat162(h0, h1);
            *(__nv_bfloat162*)(g_al + r1 + cc) = __halves2bfloat162(l0, l1);
        }
    }

    // fused normalize + zero-fill epilogue (e tiles hot in L2)
    __syncthreads();

    const size_t rowbase = (size_t)bh * S_ + (size_t)qt * 128;
    for (int rr = w; rr < 128; rr += 8) {
        const float rl = rlrow[rr];
        const int kt_last = (qt * 128 + (rr & ~15) + 15) >> 6;
        const int wspan   = (kt_last + 1) << 6;
        float* row = attnP + (rowbase + rr) * S_;
#pragma unroll 4
        for (int c = lane * 4; c < wspan; c += 128) {
            float4 v = *(float4*)(row + c);
            v.x *= rl; v.y *= rl; v.z *= rl; v.w *= rl;
            *(float4*)(row + c) = v;
        }
        const float4 z4 = make_float4(0.f, 0.f, 0.f, 0.f);
#pragma unroll 4
        for (int c = wspan + lane * 4; c < S_; c += 128) {
            *(float4*)(row + c) = z4;
        }
    }
}

// ---------------------------------------------------------------------------
extern "C" void kernel_launch(void* const* d_in, const int* in_sizes, int n_in,
                              void* d_out, int out_size)
{
    long long sz[16];
    int n = (n_in < 16) ? n_in : 16;
    for (int i = 0; i < n; i++) sz[i] = (long long)in_sizes[i];

    int ib = 0;
    for (int i = 1; i < n; i++) if (sz[i] < sz[ib]) ib = i;
    int iq = -1, iw = -1;
    for (int i = 0; i < n; i++)
        for (int j = 0; j < n; j++)
            if (i != j && i != ib && j != ib && sz[i] == 3 * sz[j]) { iq = i; iw = j; }
    int ix = -1;
    for (int i = 0; i < n; i++) {
        if (i == ib || i == iq || i == iw) continue;
        if (sz[i] == 4194304LL || sz[i] == 16777216LL) ix = i;
    }

    const float *x, *W_qkv, *W_out, *b_out;
    if (n_in >= 5 && iq >= 0 && iw >= 0 && ix >= 0) {
        x     = (const float*)d_in[ix];
        W_qkv = (const float*)d_in[iq];
        W_out = (const float*)d_in[iw];
        b_out = (const float*)d_in[ib];
    } else {
        x     = (const float*)d_in[0];
        W_qkv = (const float*)d_in[2];
        W_out = (const float*)d_in[3];
        b_out = (const float*)d_in[4];
    }

    float* ctx_out = (float*)d_out;
    float* attnP   = (float*)d_out + CTX_ELEMS;

    // 0) fp32 -> bf16 hi/lo conversions
    convert_kernel<<<512, 256>>>(x,     MS_ * D_ / 4,     0);
    convert_kernel<<<512, 256>>>(W_qkv, D_ * 3 * D_ / 4,  1);
    convert_kernel<<<512, 256>>>(W_out, D_ * D_ / 4,      2);

    const int gsmem = (2 * GA_STG + 2 * GB_STG) * 2;   // 59,392 B
    cudaFuncSetAttribute(tc_gemm_bf16, cudaFuncAttributeMaxDynamicSharedMemorySize, gsmem);

    // 1) QKV projection -> bf16 hi/lo q,k,v  (grid 48 x 32)
    {
        dim3 grid(3 * D_ / 64, MS_ / 128);
        tc_gemm_bf16<<<grid, 256, gsmem>>>(nullptr, nullptr, 3 * D_, 1);
    }
    // 2) fused attention + in-kernel normalize/zero
    {
        const int psmem = (2 * 128 * TSTR + 4 * KSTAGE) * 2;   // 110,592 B
        cudaFuncSetAttribute(pv_fused, cudaFuncAttributeMaxDynamicSharedMemorySize, psmem);
        dim3 grid(16, BH_);
        pv_fused<<<grid, 256, psmem>>>(attnP);
    }
    // 3) Output projection + bias  (grid 16 x 32)
    {
        dim3 grid(D_ / 64, MS_ / 128);
        tc_gemm_bf16<<<grid, 256, gsmem>>>(b_out, ctx_out, D_, 2);
    }
}

// round 16
// speedup vs baseline: 1.0145x; 1.0145x over previous
#include <cuda_runtime.h>
#include <cuda_bf16.h>
#include <math_constants.h>

// Problem constants
#define B_  2
#define S_  2048
#define D_  1024
#define H_  16
#define HD_ 64
#define BH_ (B_ * H_)          // 32
#define MS_ (B_ * S_)          // 4096
#define CTX_ELEMS  (4194304LL)

// NOTE (R13): harness compiles at compute_103 (no 'a'); tcgen05 unavailable.

// Scratch (device globals, 16B-aligned). NEVER pass these as kernel args from
// host (host shadow + GB300 ATS serves zeros) — resolve inside kernels.
__device__ __align__(16) __nv_bfloat16 g_qh[BH_ * S_ * HD_];
__device__ __align__(16) __nv_bfloat16 g_ql[BH_ * S_ * HD_];
__device__ __align__(16) __nv_bfloat16 g_kh[BH_ * S_ * HD_];
__device__ __align__(16) __nv_bfloat16 g_kl[BH_ * S_ * HD_];
__device__ __align__(16) __nv_bfloat16 g_vh[BH_ * S_ * HD_];
__device__ __align__(16) __nv_bfloat16 g_vl[BH_ * S_ * HD_];
__device__ __align__(16) __nv_bfloat16 g_ah[MS_ * D_];      // A operand: x, then ctx
__device__ __align__(16) __nv_bfloat16 g_al[MS_ * D_];
__device__ __align__(16) __nv_bfloat16 g_w1h[D_ * 3 * D_];
__device__ __align__(16) __nv_bfloat16 g_w1l[D_ * 3 * D_];
__device__ __align__(16) __nv_bfloat16 g_w2h[D_ * D_];
__device__ __align__(16) __nv_bfloat16 g_w2l[D_ * D_];

// ---------------------------------------------------------------------------
__device__ __forceinline__ unsigned su32(const void* p) {
    return (unsigned)__cvta_generic_to_shared(p);
}

#define LDSM4(r0, r1, r2, r3, addr)                                          \
    asm volatile("ldmatrix.sync.aligned.m8n8.x4.shared.b16 {%0,%1,%2,%3},[%4];" \
                 : "=r"(r0), "=r"(r1), "=r"(r2), "=r"(r3) : "r"(addr))

#define LDSM2(r0, r1, addr)                                                  \
    asm volatile("ldmatrix.sync.aligned.m8n8.x2.shared.b16 {%0,%1},[%2];"    \
                 : "=r"(r0), "=r"(r1) : "r"(addr))

#define LDSM2T(r0, r1, addr)                                                 \
    asm volatile("ldmatrix.sync.aligned.m8n8.x2.trans.shared.b16 {%0,%1},[%2];" \
                 : "=r"(r0), "=r"(r1) : "r"(addr))

#define MMA16816(d, a, b)                                                    \
    asm volatile("mma.sync.aligned.m16n8k16.row.col.f32.bf16.bf16.f32 "      \
                 "{%0,%1,%2,%3},{%4,%5,%6,%7},{%8,%9},{%0,%1,%2,%3};"        \
                 : "+f"(d[0]), "+f"(d[1]), "+f"(d[2]), "+f"(d[3])            \
                 : "r"(a[0]), "r"(a[1]), "r"(a[2]), "r"(a[3]),               \
                   "r"(b[0]), "r"(b[1]))

#define CP_ASYNC16(saddr, gptr)                                              \
    asm volatile("cp.async.cg.shared.global [%0], [%1], 16;"                 \
                 :: "r"(saddr), "l"(gptr))
#define CP_COMMIT()  asm volatile("cp.async.commit_group;")
#define CP_WAIT(N)   asm volatile("cp.async.wait_group %0;" :: "n"(N))

__device__ __forceinline__ void f2bf2(float v, __nv_bfloat16& h, __nv_bfloat16& l) {
    h = __float2bfloat16_rn(v);
    l = __float2bfloat16_rn(v - __bfloat162float(h));
}

__device__ __forceinline__ unsigned packbf(__nv_bfloat16 a, __nv_bfloat16 b) {
    __nv_bfloat162 t = __halves2bfloat162(a, b);
    return *(unsigned*)&t;
}

// pv smem geometry
#define TSTR 72
#define TPLANE (64 * TSTR)
#define TPLANE_B (TPLANE * 2)
#define KSTAGE (2 * TPLANE)

// ---------------------------------------------------------------------------
// convert: fp32 -> bf16 hi/lo planes. which: 0=g_ah/g_al, 1=W_qkv, 2=W_out
// ---------------------------------------------------------------------------
__global__ void convert_kernel(const float* __restrict__ src, int n4, int which)
{
    __nv_bfloat162* dh;
    __nv_bfloat162* dl;
    if (which == 0)      { dh = (__nv_bfloat162*)g_ah;  dl = (__nv_bfloat162*)g_al;  }
    else if (which == 1) { dh = (__nv_bfloat162*)g_w1h; dl = (__nv_bfloat162*)g_w1l; }
    else                 { dh = (__nv_bfloat162*)g_w2h; dl = (__nv_bfloat162*)g_w2l; }

    int stride = gridDim.x * blockDim.x;
    for (int i = blockIdx.x * blockDim.x + threadIdx.x; i < n4; i += stride) {
        float4 v = *(const float4*)(src + 4 * (size_t)i);
        __nv_bfloat16 h0, l0, h1, l1, h2, l2, h3, l3;
        f2bf2(v.x, h0, l0); f2bf2(v.y, h1, l1);
        f2bf2(v.z, h2, l2); f2bf2(v.w, h3, l3);
        dh[2 * i]     = __halves2bfloat162(h0, h1);
        dh[2 * i + 1] = __halves2bfloat162(h2, h3);
        dl[2 * i]     = __halves2bfloat162(l0, l1);
        dl[2 * i + 1] = __halves2bfloat162(l2, l3);
    }
}

// ---------------------------------------------------------------------------
// tc_gemm_bf16: 128x64 tile, 3-stage cp.async pipeline, ONE barrier/iter.
// mode 1: scatter q/k/v hi/lo;  mode 2: C = A@W + bias.
// ---------------------------------------------------------------------------
#define GA_STG (2 * 128 * 40)            // elems per A stage (hi+lo)
#define GB_STG (2 * 32 * 72)             // elems per B stage (hi+lo)
#define STG_EL (GA_STG + GB_STG)         // elems per full stage
#define STG_B  (STG_EL * 2)              // bytes per full stage
#define GA_LO  (128 * 40 * 2)            // bytes hi->lo within A stage
#define GB_LO  (32 * 72 * 2)             // bytes hi->lo within B stage

__global__ __launch_bounds__(256, 2)
void tc_gemm_bf16(const float* __restrict__ bias, float* __restrict__ C,
                  int N, int mode)
{
    extern __shared__ __nv_bfloat16 gsm[];   // 3 stages: [A | B] each

    const __nv_bfloat16* Wh = (mode == 1) ? g_w1h : g_w2h;
    const __nv_bfloat16* Wl = (mode == 1) ? g_w1l : g_w2l;
    const int K = 1024;

    const int tid  = threadIdx.x;
    const int lane = tid & 31;
    const int w    = tid >> 5;
    const int wm   = w >> 1;
    const int wn   = w & 1;
    const int m0   = blockIdx.y * 128;
    const int n0   = blockIdx.x * 64;

    float acc[2][4][4];
#pragma unroll
    for (int i = 0; i < 2; i++)
#pragma unroll
        for (int j = 0; j < 4; j++)
#pragma unroll
            for (int r = 0; r < 4; r++) acc[i][j][r] = 0.f;

    // hoisted staging addressing (stage-0 smem addresses; +s*STG_B per stage)
    const __nv_bfloat16* srcA[4]; unsigned dstA[4];
    const __nv_bfloat16* srcB[2]; unsigned dstB[2];
#pragma unroll
    for (int u = 0; u < 4; u++) {
        int id = u * 256 + tid;
        int pl = id >> 9, wi = id & 511;
        int row = wi >> 2, c = wi & 3;
        srcA[u] = (pl ? g_al : g_ah) + (size_t)(m0 + row) * K + c * 8;
        dstA[u] = su32(gsm + pl * (128 * 40) + row * 40 + c * 8);
    }
#pragma unroll
    for (int u = 0; u < 2; u++) {
        int id = u * 256 + tid;
        int pl = id >> 8, wi = id & 255;
        int row = wi >> 3, c = wi & 7;
        srcB[u] = (pl ? Wl : Wh) + (size_t)row * N + n0 + c * 8;
        dstB[u] = su32(gsm + GA_STG + pl * (32 * 72) + row * 72 + c * 8);
    }

    auto stage = [&](int s, int k0) {
        unsigned so = (unsigned)s * STG_B;
        size_t bstep = (size_t)k0 * N;
#pragma unroll
        for (int u = 0; u < 4; u++) CP_ASYNC16(dstA[u] + so, srcA[u] + k0);
#pragma unroll
        for (int u = 0; u < 2; u++) CP_ASYNC16(dstB[u] + so, srcB[u] + bstep);
        CP_COMMIT();
    };

    stage(0, 0);
    stage(1, 32);

    const unsigned aBase = su32(gsm + (wm * 32 + (lane & 15)) * 40 + (lane >> 4) * 8);
    const unsigned bBase = su32(gsm + GA_STG + (lane & 15) * 72 + wn * 32);

    for (int it = 0; it < 32; it++) {
        if (it < 31) { CP_WAIT(1); }     // stage(it) complete; stage(it+1) may fly
        else         { CP_WAIT(0); }
        __syncthreads();                 // single barrier per iteration
        if (it + 2 < 32) stage((it + 2) % 3, (it + 2) * 32);

        const unsigned so = (unsigned)(it % 3) * STG_B;
        const unsigned aS = aBase + so;
        const unsigned bS = bBase + so;

#pragma unroll
        for (int ks = 0; ks < 32; ks += 16) {
            unsigned bh2[4][2], bl2[4][2];
#pragma unroll
            for (int j = 0; j < 4; j++) {
                unsigned ba = bS + (unsigned)(ks * 72 + j * 8) * 2;
                LDSM2T(bh2[j][0], bh2[j][1], ba);
                LDSM2T(bl2[j][0], bl2[j][1], ba + GB_LO);
            }
#pragma unroll
            for (int i = 0; i < 2; i++) {
                unsigned ah[4], al[4];
                unsigned aa = aS + (unsigned)(i * 16 * 40 + ks) * 2;
                LDSM4(ah[0], ah[1], ah[2], ah[3], aa);
                LDSM4(al[0], al[1], al[2], al[3], aa + GA_LO);
#pragma unroll
                for (int j = 0; j < 4; j++) {
                    MMA16816(acc[i][j], ah, bh2[j]);
                    MMA16816(acc[i][j], ah, bl2[j]);
                    MMA16816(acc[i][j], al, bh2[j]);
                }
            }
        }
    }

    const int g = lane >> 2, tg = lane & 3;
    if (mode == 1) {
#pragma unroll
        for (int i = 0; i < 2; i++) {
            int mrow = m0 + wm * 32 + i * 16 + g;
            int b = mrow >> 11, s = mrow & (S_ - 1);
#pragma unroll
            for (int j = 0; j < 4; j++) {
                int c = n0 + wn * 32 + j * 8 + tg * 2;
                int sec = c >> 10;
                int within = c & 1023;
                int h = within >> 6, hd = within & 63;
                __nv_bfloat16 *oh, *ol;
                if (sec == 0)      { oh = g_qh; ol = g_ql; }
                else if (sec == 1) { oh = g_kh; ol = g_kl; }
                else               { oh = g_vh; ol = g_vl; }
                size_t base = ((size_t)(b * H_ + h) * S_ + s) * HD_ + hd;
                __nv_bfloat16 h0, l0, h1, l1;
                f2bf2(acc[i][j][0], h0, l0); f2bf2(acc[i][j][1], h1, l1);
                *(__nv_bfloat162*)(oh + base) = __halves2bfloat162(h0, h1);
                *(__nv_bfloat162*)(ol + base) = __halves2bfloat162(l0, l1);
                f2bf2(acc[i][j][2], h0, l0); f2bf2(acc[i][j][3], h1, l1);
                *(__nv_bfloat162*)(oh + base + 512) = __halves2bfloat162(h0, h1);
                *(__nv_bfloat162*)(ol + base + 512) = __halves2bfloat162(l0, l1);
            }
        }
    } else {
#pragma unroll
        for (int i = 0; i < 2; i++) {
            int mrow = m0 + wm * 32 + i * 16 + g;
#pragma unroll
            for (int j = 0; j < 4; j++) {
                int c = n0 + wn * 32 + j * 8 + tg * 2;
                float2 bv = *(const float2*)(bias + c);
                *(float2*)(C + (size_t)mrow * N + c) =
                    make_float2(acc[i][j][0] + bv.x, acc[i][j][1] + bv.y);
                *(float2*)(C + (size_t)(mrow + 8) * N + c) =
                    make_float2(acc[i][j][2] + bv.x, acc[i][j][3] + bv.y);
            }
        }
    }
}

// ---------------------------------------------------------------------------
// pv_fused: 128-q-row tiles, max-free softmax, ONE barrier per kt iteration,
// fused normalize + zero-fill epilogue.
// ---------------------------------------------------------------------------
__global__ __launch_bounds__(256, 2)
void pv_fused(float* __restrict__ attnP)
{
    extern __shared__ __nv_bfloat16 psm[];
    __nv_bfloat16* Qs = psm;
    __nv_bfloat16* Kr = Qs + 2 * 128 * TSTR;
    __nv_bfloat16* Vr = Kr + 2 * KSTAGE;
    __shared__ float rlrow[128];

    const int qt   = 15 - blockIdx.x;
    const int bh   = blockIdx.y;
    const int tid  = threadIdx.x;
    const int lane = tid & 31;
    const int w    = tid >> 5;
    const int lr   = lane >> 2, lc = lane & 3;
    const int nkt  = 2 * qt + 2;

    const __nv_bfloat16* srcKV[8]; unsigned dstKV[8];
    {
        const size_t gb = (size_t)bh * S_ * HD_;
#pragma unroll
        for (int u = 0; u < 8; u++) {
            int id = u * 256 + tid;
            int pl = id >> 9, wi = id & 511;
            int row = wi >> 3, c8 = (wi & 7) * 8;
            srcKV[u] = (pl == 0 ? g_kh : pl == 1 ? g_kl : pl == 2 ? g_vh : g_vl)
                       + gb + row * HD_ + c8;
            dstKV[u] = su32(((pl < 2) ? Kr : Vr) + (pl & 1) * TPLANE + row * TSTR + c8);
        }
    }
    auto prefetch = [&](int kt) {
        unsigned so = (kt & 1) ? (unsigned)(KSTAGE * 2) : 0u;
        int go = kt * (64 * HD_);
#pragma unroll
        for (int u = 0; u < 8; u++) CP_ASYNC16(dstKV[u] + so, srcKV[u] + go);
        CP_COMMIT();
    };

    prefetch(0);

    {
        const size_t qoff = ((size_t)bh * S_ + qt * 128) * HD_;
#pragma unroll
        for (int u = 0; u < 4; u++) {
            int id = u * 256 + tid;
            int row = id >> 3, c8 = (id & 7) * 8;
            *(int4*)(Qs + row * TSTR + c8) =
                *(const int4*)(g_qh + qoff + row * HD_ + c8);
            *(int4*)(Qs + 128 * TSTR + row * TSTR + c8) =
                *(const int4*)(g_ql + qoff + row * HD_ + c8);
        }
    }
    __syncthreads();

    unsigned qh[4][4], ql[4][4];
#pragma unroll
    for (int ks = 0; ks < 4; ks++) {
        unsigned a = su32(Qs + (w * 16 + (lane & 15)) * TSTR + (lane >> 4) * 8 + ks * 16);
        LDSM4(qh[ks][0], qh[ks][1], qh[ks][2], qh[ks][3], a);
        LDSM4(ql[ks][0], ql[ks][1], ql[ks][2], ql[ks][3], a + 128 * TSTR * 2);
    }

    const int qbase = qt * 128 + w * 16;
    const int qg0 = qbase + lr;
    const int qg1 = qg0 + 8;
    const size_t arow0 = ((size_t)bh * S_ + qg0) * S_;
    const size_t arow1 = ((size_t)bh * S_ + qg1) * S_;

    float oacc[8][4];
#pragma unroll
    for (int j = 0; j < 8; j++)
#pragma unroll
        for (int r = 0; r < 4; r++) oacc[j][r] = 0.f;

    float lsum0 = 0.f, lsum1 = 0.f;

    for (int kt = 0; kt < nkt; kt++) {
        CP_WAIT(0);                      // stage(kt) data landed
        __syncthreads();                 // single barrier per iteration
        if (kt + 1 < nkt) prefetch(kt + 1);   // overlaps compute below

        if (64 * kt <= qbase + 15) {
            const __nv_bfloat16* Ks = Kr + (kt & 1) * KSTAGE;
            const __nv_bfloat16* Vs = Vr + (kt & 1) * KSTAGE;

#pragma unroll
            for (int hh = 0; hh < 2; hh++) {
                float sacc[4][4];
#pragma unroll
                for (int j = 0; j < 4; j++)
#pragma unroll
                    for (int r = 0; r < 4; r++) sacc[j][r] = 0.f;
#pragma unroll
                for (int ks = 0; ks < 4; ks++) {
#pragma unroll
                    for (int j = 0; j < 4; j++) {
                        unsigned addr = su32(Ks + (hh * 32 + j * 8 + (lane & 7)) * TSTR
                                             + ks * 16 + ((lane >> 3) & 1) * 8);
                        unsigned bhf[2], blf[2];
                        LDSM2(bhf[0], bhf[1], addr);
                        LDSM2(blf[0], blf[1], addr + TPLANE_B);
                        MMA16816(sacc[j], qh[ks], bhf);
                        MMA16816(sacc[j], qh[ks], blf);
                        MMA16816(sacc[j], ql[ks], bhf);
                    }
                }

                float p[4][4];
#pragma unroll
                for (int j = 0; j < 4; j++) {
                    int kg = kt * 64 + hh * 32 + j * 8 + lc * 2;
                    p[j][0] = (kg     <= qg0) ? __expf(sacc[j][0] * 0.125f) : 0.f;
                    p[j][1] = (kg + 1 <= qg0) ? __expf(sacc[j][1] * 0.125f) : 0.f;
                    p[j][2] = (kg     <= qg1) ? __expf(sacc[j][2] * 0.125f) : 0.f;
                    p[j][3] = (kg + 1 <= qg1) ? __expf(sacc[j][3] * 0.125f) : 0.f;
                    lsum0 += p[j][0] + p[j][1];
                    lsum1 += p[j][2] + p[j][3];
                    *(float2*)(attnP + arow0 + kg) = make_float2(p[j][0], p[j][1]);
                    *(float2*)(attnP + arow1 + kg) = make_float2(p[j][2], p[j][3]);
                }

#pragma unroll
                for (int g = 0; g < 2; g++) {
                    int j0 = 2 * g, j1 = 2 * g + 1;
                    __nv_bfloat16 h00, l00, h01, l01, h02, l02, h03, l03;
                    __nv_bfloat16 h10, l10, h11, l11, h12, l12, h13, l13;
                    f2bf2(p[j0][0], h00, l00); f2bf2(p[j0][1], h01, l01);
                    f2bf2(p[j0][2], h02, l02); f2bf2(p[j0][3], h03, l03);
                    f2bf2(p[j1][0], h10, l10); f2bf2(p[j1][1], h11, l11);
                    f2bf2(p[j1][2], h12, l12); f2bf2(p[j1][3], h13, l13);
                    unsigned aph[4] = { packbf(h00, h01), packbf(h02, h03),
                                        packbf(h10, h11), packbf(h12, h13) };
                    unsigned apl[4] = { packbf(l00, l01), packbf(l02, l03),
                                        packbf(l10, l11), packbf(l12, l13) };
#pragma unroll
                    for (int j2 = 0; j2 < 8; j2++) {
                        unsigned va = su32(Vs + (hh * 32 + g * 16 + (lane & 15)) * TSTR + j2 * 8);
                        unsigned bvh[2], bvl[2];
                        LDSM2T(bvh[0], bvh[1], va);
                        LDSM2T(bvl[0], bvl[1], va + TPLANE_B);
                        MMA16816(oacc[j2], aph, bvh);
                        MMA16816(oacc[j2], aph, bvl);
                        MMA16816(oacc[j2], apl, bvh);
                    }
                }
            }
        }
    }

#pragma unroll
    for (int d = 1; d <= 2; d <<= 1) {
        lsum0 += __shfl_xor_sync(0xffffffffu, lsum0, d);
        lsum1 += __shfl_xor_sync(0xffffffffu, lsum1, d);
    }
    const float rl0 = 1.f / lsum0;
    const float rl1 = 1.f / lsum1;
    if (lc == 0) {
        rlrow[w * 16 + lr]     = rl0;
        rlrow[w * 16 + lr + 8] = rl1;
    }

    {
        const int b = bh >> 4, h = bh & 15;
        const size_t r0 = ((size_t)(b * S_ + qg0)) * D_ + h * HD_;
        const size_t r1 = ((size_t)(b * S_ + qg1)) * D_ + h * HD_;
#pragma unroll
        for (int j2 = 0; j2 < 8; j2++) {
            int cc = j2 * 8 + lc * 2;
            __nv_bfloat16 h0, l0, h1, l1;
            f2bf2(oacc[j2][0] * rl0, h0, l0); f2bf2(oacc[j2][1] * rl0, h1, l1);
            *(__nv_bfloat162*)(g_ah + r0 + cc) = __halves2bfloat162(h0, h1);
            *(__nv_bfloat162*)(g_al + r0 + cc) = __halves2bfloat162(l0, l1);
            f2bf2(oacc[j2][2] * rl1, h0, l0); f2bf2(oacc[j2][3] * rl1, h1, l1);
            *(__nv_bfloat162*)(g_ah + r1 + cc) = __halves2bfloat162(h0, h1);
            *(__nv_bfloat162*)(g_al + r1 + cc) = __halves2bfloat162(l0, l1);
        }
    }

    // fused normalize + zero-fill epilogue (e tiles hot in L2)
    __syncthreads();

    const size_t rowbase = (size_t)bh * S_ + (size_t)qt * 128;
    for (int rr = w; rr < 128; rr += 8) {
        const float rl = rlrow[rr];
        const int kt_last = (qt * 128 + (rr & ~15) + 15) >> 6;
        const int wspan   = (kt_last + 1) << 6;
        float* row = attnP + (rowbase + rr) * S_;
#pragma unroll 4
        for (int c = lane * 4; c < wspan; c += 128) {
            float4 v = *(float4*)(row + c);
            v.x *= rl; v.y *= rl; v.z *= rl; v.w *= rl;
            *(float4*)(row + c) = v;
        }
        const float4 z4 = make_float4(0.f, 0.f, 0.f, 0.f);
#pragma unroll 4
        for (int c = wspan + lane * 4; c < S_; c += 128) {
            *(float4*)(row + c) = z4;
        }
    }
}

// ---------------------------------------------------------------------------
extern "C" void kernel_launch(void* const* d_in, const int* in_sizes, int n_in,
                              void* d_out, int out_size)
{
    long long sz[16];
    int n = (n_in < 16) ? n_in : 16;
    for (int i = 0; i < n; i++) sz[i] = (long long)in_sizes[i];

    int ib = 0;
    for (int i = 1; i < n; i++) if (sz[i] < sz[ib]) ib = i;
    int iq = -1, iw = -1;
    for (int i = 0; i < n; i++)
        for (int j = 0; j < n; j++)
            if (i != j && i != ib && j != ib && sz[i] == 3 * sz[j]) { iq = i; iw = j; }
    int ix = -1;
    for (int i = 0; i < n; i++) {
        if (i == ib || i == iq || i == iw) continue;
        if (sz[i] == 4194304LL || sz[i] == 16777216LL) ix = i;
    }

    const float *x, *W_qkv, *W_out, *b_out;
    if (n_in >= 5 && iq >= 0 && iw >= 0 && ix >= 0) {
        x     = (const float*)d_in[ix];
        W_qkv = (const float*)d_in[iq];
        W_out = (const float*)d_in[iw];
        b_out = (const float*)d_in[ib];
    } else {
        x     = (const float*)d_in[0];
        W_qkv = (const float*)d_in[2];
        W_out = (const float*)d_in[3];
        b_out = (const float*)d_in[4];
    }

    float* ctx_out = (float*)d_out;
    float* attnP   = (float*)d_out + CTX_ELEMS;

    // 0) fp32 -> bf16 hi/lo conversions
    convert_kernel<<<512, 256>>>(x,     MS_ * D_ / 4,     0);
    convert_kernel<<<512, 256>>>(W_qkv, D_ * 3 * D_ / 4,  1);
    convert_kernel<<<512, 256>>>(W_out, D_ * D_ / 4,      2);

    const int gsmem = 3 * STG_B;   // 89,088 B (3 stages)
    cudaFuncSetAttribute(tc_gemm_bf16, cudaFuncAttributeMaxDynamicSharedMemorySize, gsmem);

    // 1) QKV projection -> bf16 hi/lo q,k,v  (grid 48 x 32)
    {
        dim3 grid(3 * D_ / 64, MS_ / 128);
        tc_gemm_bf16<<<grid, 256, gsmem>>>(nullptr, nullptr, 3 * D_, 1);
    }
    // 2) fused attention + in-kernel normalize/zero
    {
        const int psmem = (2 * 128 * TSTR + 4 * KSTAGE) * 2;   // 110,592 B
        cudaFuncSetAttribute(pv_fused, cudaFuncAttributeMaxDynamicSharedMemorySize, psmem);
        dim3 grid(16, BH_);
        pv_fused<<<grid, 256, psmem>>>(attnP);
    }
    // 3) Output projection + bias  (grid 16 x 32)
    {
        dim3 grid(D_ / 64, MS_ / 128);
        tc_gemm_bf16<<<grid, 256, gsmem>>>(b_out, ctx_out, D_, 2);
    }
}

// round 17
// speedup vs baseline: 1.0210x; 1.0064x over previous
#include <cuda_runtime.h>
#include <cuda_bf16.h>
#include <math_constants.h>

// Problem constants
#define B_  2
#define S_  2048
#define D_  1024
#define H_  16
#define HD_ 64
#define BH_ (B_ * H_)          // 32
#define MS_ (B_ * S_)          // 4096
#define CTX_ELEMS  (4194304LL)

// NOTE (R13): harness compiles at compute_103 (no 'a'); tcgen05 unavailable.

// Scratch (device globals, 16B-aligned). NEVER pass these as kernel args from
// host (host shadow + GB300 ATS serves zeros) — resolve inside kernels.
__device__ __align__(16) __nv_bfloat16 g_qh[BH_ * S_ * HD_];
__device__ __align__(16) __nv_bfloat16 g_ql[BH_ * S_ * HD_];
__device__ __align__(16) __nv_bfloat16 g_kh[BH_ * S_ * HD_];
__device__ __align__(16) __nv_bfloat16 g_kl[BH_ * S_ * HD_];
__device__ __align__(16) __nv_bfloat16 g_vh[BH_ * S_ * HD_];
__device__ __align__(16) __nv_bfloat16 g_vl[BH_ * S_ * HD_];
__device__ __align__(16) __nv_bfloat16 g_ah[MS_ * D_];      // A operand: x, then ctx
__device__ __align__(16) __nv_bfloat16 g_al[MS_ * D_];
__device__ __align__(16) __nv_bfloat16 g_w1h[D_ * 3 * D_];
__device__ __align__(16) __nv_bfloat16 g_w1l[D_ * 3 * D_];
__device__ __align__(16) __nv_bfloat16 g_w2h[D_ * D_];
__device__ __align__(16) __nv_bfloat16 g_w2l[D_ * D_];

// ---------------------------------------------------------------------------
__device__ __forceinline__ unsigned su32(const void* p) {
    return (unsigned)__cvta_generic_to_shared(p);
}

#define LDSM4(r0, r1, r2, r3, addr)                                          \
    asm volatile("ldmatrix.sync.aligned.m8n8.x4.shared.b16 {%0,%1,%2,%3},[%4];" \
                 : "=r"(r0), "=r"(r1), "=r"(r2), "=r"(r3) : "r"(addr))

#define LDSM2(r0, r1, addr)                                                  \
    asm volatile("ldmatrix.sync.aligned.m8n8.x2.shared.b16 {%0,%1},[%2];"    \
                 : "=r"(r0), "=r"(r1) : "r"(addr))

#define LDSM2T(r0, r1, addr)                                                 \
    asm volatile("ldmatrix.sync.aligned.m8n8.x2.trans.shared.b16 {%0,%1},[%2];" \
                 : "=r"(r0), "=r"(r1) : "r"(addr))

#define MMA16816(d, a, b)                                                    \
    asm volatile("mma.sync.aligned.m16n8k16.row.col.f32.bf16.bf16.f32 "      \
                 "{%0,%1,%2,%3},{%4,%5,%6,%7},{%8,%9},{%0,%1,%2,%3};"        \
                 : "+f"(d[0]), "+f"(d[1]), "+f"(d[2]), "+f"(d[3])            \
                 : "r"(a[0]), "r"(a[1]), "r"(a[2]), "r"(a[3]),               \
                   "r"(b[0]), "r"(b[1]))

#define CP_ASYNC16(saddr, gptr)                                              \
    asm volatile("cp.async.cg.shared.global [%0], [%1], 16;"                 \
                 :: "r"(saddr), "l"(gptr))
#define CP_COMMIT()  asm volatile("cp.async.commit_group;")
#define CP_WAIT(N)   asm volatile("cp.async.wait_group %0;" :: "n"(N))

__device__ __forceinline__ void f2bf2(float v, __nv_bfloat16& h, __nv_bfloat16& l) {
    h = __float2bfloat16_rn(v);
    l = __float2bfloat16_rn(v - __bfloat162float(h));
}

__device__ __forceinline__ unsigned packbf(__nv_bfloat16 a, __nv_bfloat16 b) {
    __nv_bfloat162 t = __halves2bfloat162(a, b);
    return *(unsigned*)&t;
}

// pv smem geometry
#define TSTR 72
#define TPLANE (64 * TSTR)
#define TPLANE_B (TPLANE * 2)
#define KSTAGE (2 * TPLANE)

// ---------------------------------------------------------------------------
// convert: fp32 -> bf16 hi/lo planes. which: 0=g_ah/g_al, 1=W_qkv, 2=W_out
// ---------------------------------------------------------------------------
__global__ void convert_kernel(const float* __restrict__ src, int n4, int which)
{
    __nv_bfloat162* dh;
    __nv_bfloat162* dl;
    if (which == 0)      { dh = (__nv_bfloat162*)g_ah;  dl = (__nv_bfloat162*)g_al;  }
    else if (which == 1) { dh = (__nv_bfloat162*)g_w1h; dl = (__nv_bfloat162*)g_w1l; }
    else                 { dh = (__nv_bfloat162*)g_w2h; dl = (__nv_bfloat162*)g_w2l; }

    int stride = gridDim.x * blockDim.x;
    for (int i = blockIdx.x * blockDim.x + threadIdx.x; i < n4; i += stride) {
        float4 v = *(const float4*)(src + 4 * (size_t)i);
        __nv_bfloat16 h0, l0, h1, l1, h2, l2, h3, l3;
        f2bf2(v.x, h0, l0); f2bf2(v.y, h1, l1);
        f2bf2(v.z, h2, l2); f2bf2(v.w, h3, l3);
        dh[2 * i]     = __halves2bfloat162(h0, h1);
        dh[2 * i + 1] = __halves2bfloat162(h2, h3);
        dl[2 * i]     = __halves2bfloat162(l0, l1);
        dl[2 * i + 1] = __halves2bfloat162(l2, l3);
    }
}

// ---------------------------------------------------------------------------
// tc_gemm_bf16: 128x64 tile, 3-stage cp.async pipeline, ONE barrier/iter.
// MMA issue reordered into three passes to break accumulator RAW chains.
// ---------------------------------------------------------------------------
#define GA_STG (2 * 128 * 40)
#define GB_STG (2 * 32 * 72)
#define STG_EL (GA_STG + GB_STG)
#define STG_B  (STG_EL * 2)
#define GA_LO  (128 * 40 * 2)
#define GB_LO  (32 * 72 * 2)

__global__ __launch_bounds__(256, 2)
void tc_gemm_bf16(const float* __restrict__ bias, float* __restrict__ C,
                  int N, int mode)
{
    extern __shared__ __nv_bfloat16 gsm[];

    const __nv_bfloat16* Wh = (mode == 1) ? g_w1h : g_w2h;
    const __nv_bfloat16* Wl = (mode == 1) ? g_w1l : g_w2l;
    const int K = 1024;

    const int tid  = threadIdx.x;
    const int lane = tid & 31;
    const int w    = tid >> 5;
    const int wm   = w >> 1;
    const int wn   = w & 1;
    const int m0   = blockIdx.y * 128;
    const int n0   = blockIdx.x * 64;

    float acc[2][4][4];
#pragma unroll
    for (int i = 0; i < 2; i++)
#pragma unroll
        for (int j = 0; j < 4; j++)
#pragma unroll
            for (int r = 0; r < 4; r++) acc[i][j][r] = 0.f;

    const __nv_bfloat16* srcA[4]; unsigned dstA[4];
    const __nv_bfloat16* srcB[2]; unsigned dstB[2];
#pragma unroll
    for (int u = 0; u < 4; u++) {
        int id = u * 256 + tid;
        int pl = id >> 9, wi = id & 511;
        int row = wi >> 2, c = wi & 3;
        srcA[u] = (pl ? g_al : g_ah) + (size_t)(m0 + row) * K + c * 8;
        dstA[u] = su32(gsm + pl * (128 * 40) + row * 40 + c * 8);
    }
#pragma unroll
    for (int u = 0; u < 2; u++) {
        int id = u * 256 + tid;
        int pl = id >> 8, wi = id & 255;
        int row = wi >> 3, c = wi & 7;
        srcB[u] = (pl ? Wl : Wh) + (size_t)row * N + n0 + c * 8;
        dstB[u] = su32(gsm + GA_STG + pl * (32 * 72) + row * 72 + c * 8);
    }

    auto stage = [&](int s, int k0) {
        unsigned so = (unsigned)s * STG_B;
        size_t bstep = (size_t)k0 * N;
#pragma unroll
        for (int u = 0; u < 4; u++) CP_ASYNC16(dstA[u] + so, srcA[u] + k0);
#pragma unroll
        for (int u = 0; u < 2; u++) CP_ASYNC16(dstB[u] + so, srcB[u] + bstep);
        CP_COMMIT();
    };

    stage(0, 0);
    stage(1, 32);

    const unsigned aBase = su32(gsm + (wm * 32 + (lane & 15)) * 40 + (lane >> 4) * 8);
    const unsigned bBase = su32(gsm + GA_STG + (lane & 15) * 72 + wn * 32);

    for (int it = 0; it < 32; it++) {
        if (it < 31) { CP_WAIT(1); }
        else         { CP_WAIT(0); }
        __syncthreads();
        if (it + 2 < 32) stage((it + 2) % 3, (it + 2) * 32);

        const unsigned so = (unsigned)(it % 3) * STG_B;
        const unsigned aS = aBase + so;
        const unsigned bS = bBase + so;

#pragma unroll
        for (int ks = 0; ks < 32; ks += 16) {
            unsigned bh2[4][2], bl2[4][2];
#pragma unroll
            for (int j = 0; j < 4; j++) {
                unsigned ba = bS + (unsigned)(ks * 72 + j * 8) * 2;
                LDSM2T(bh2[j][0], bh2[j][1], ba);
                LDSM2T(bl2[j][0], bl2[j][1], ba + GB_LO);
            }
            unsigned ah2[2][4], al2[2][4];
#pragma unroll
            for (int i = 0; i < 2; i++) {
                unsigned aa = aS + (unsigned)(i * 16 * 40 + ks) * 2;
                LDSM4(ah2[i][0], ah2[i][1], ah2[i][2], ah2[i][3], aa);
                LDSM4(al2[i][0], al2[i][1], al2[i][2], al2[i][3], aa + GA_LO);
            }
            // three passes: dependent MMAs to the same acc are 8 apart
#pragma unroll
            for (int i = 0; i < 2; i++)
#pragma unroll
                for (int j = 0; j < 4; j++) MMA16816(acc[i][j], ah2[i], bh2[j]);
#pragma unroll
            for (int i = 0; i < 2; i++)
#pragma unroll
                for (int j = 0; j < 4; j++) MMA16816(acc[i][j], ah2[i], bl2[j]);
#pragma unroll
            for (int i = 0; i < 2; i++)
#pragma unroll
                for (int j = 0; j < 4; j++) MMA16816(acc[i][j], al2[i], bh2[j]);
        }
    }

    const int g = lane >> 2, tg = lane & 3;
    if (mode == 1) {
#pragma unroll
        for (int i = 0; i < 2; i++) {
            int mrow = m0 + wm * 32 + i * 16 + g;
            int b = mrow >> 11, s = mrow & (S_ - 1);
#pragma unroll
            for (int j = 0; j < 4; j++) {
                int c = n0 + wn * 32 + j * 8 + tg * 2;
                int sec = c >> 10;
                int within = c & 1023;
                int h = within >> 6, hd = within & 63;
                __nv_bfloat16 *oh, *ol;
                if (sec == 0)      { oh = g_qh; ol = g_ql; }
                else if (sec == 1) { oh = g_kh; ol = g_kl; }
                else               { oh = g_vh; ol = g_vl; }
                size_t base = ((size_t)(b * H_ + h) * S_ + s) * HD_ + hd;
                __nv_bfloat16 h0, l0, h1, l1;
                f2bf2(acc[i][j][0], h0, l0); f2bf2(acc[i][j][1], h1, l1);
                *(__nv_bfloat162*)(oh + base) = __halves2bfloat162(h0, h1);
                *(__nv_bfloat162*)(ol + base) = __halves2bfloat162(l0, l1);
                f2bf2(acc[i][j][2], h0, l0); f2bf2(acc[i][j][3], h1, l1);
                *(__nv_bfloat162*)(oh + base + 512) = __halves2bfloat162(h0, h1);
                *(__nv_bfloat162*)(ol + base + 512) = __halves2bfloat162(l0, l1);
            }
        }
    } else {
#pragma unroll
        for (int i = 0; i < 2; i++) {
            int mrow = m0 + wm * 32 + i * 16 + g;
#pragma unroll
            for (int j = 0; j < 4; j++) {
                int c = n0 + wn * 32 + j * 8 + tg * 2;
                float2 bv = *(const float2*)(bias + c);
                *(float2*)(C + (size_t)mrow * N + c) =
                    make_float2(acc[i][j][0] + bv.x, acc[i][j][1] + bv.y);
                *(float2*)(C + (size_t)(mrow + 8) * N + c) =
                    make_float2(acc[i][j][2] + bv.x, acc[i][j][3] + bv.y);
            }
        }
    }
}

// ---------------------------------------------------------------------------
// pv_fused: 128-q-row tiles, max-free softmax, one barrier/kt, fused
// normalize + zero-fill epilogue. MMA issue reordered (3 passes).
// ---------------------------------------------------------------------------
__global__ __launch_bounds__(256, 2)
void pv_fused(float* __restrict__ attnP)
{
    extern __shared__ __nv_bfloat16 psm[];
    __nv_bfloat16* Qs = psm;
    __nv_bfloat16* Kr = Qs + 2 * 128 * TSTR;
    __nv_bfloat16* Vr = Kr + 2 * KSTAGE;
    __shared__ float rlrow[128];

    const int qt   = 15 - blockIdx.x;
    const int bh   = blockIdx.y;
    const int tid  = threadIdx.x;
    const int lane = tid & 31;
    const int w    = tid >> 5;
    const int lr   = lane >> 2, lc = lane & 3;
    const int nkt  = 2 * qt + 2;

    const __nv_bfloat16* srcKV[8]; unsigned dstKV[8];
    {
        const size_t gb = (size_t)bh * S_ * HD_;
#pragma unroll
        for (int u = 0; u < 8; u++) {
            int id = u * 256 + tid;
            int pl = id >> 9, wi = id & 511;
            int row = wi >> 3, c8 = (wi & 7) * 8;
            srcKV[u] = (pl == 0 ? g_kh : pl == 1 ? g_kl : pl == 2 ? g_vh : g_vl)
                       + gb + row * HD_ + c8;
            dstKV[u] = su32(((pl < 2) ? Kr : Vr) + (pl & 1) * TPLANE + row * TSTR + c8);
        }
    }
    auto prefetch = [&](int kt) {
        unsigned so = (kt & 1) ? (unsigned)(KSTAGE * 2) : 0u;
        int go = kt * (64 * HD_);
#pragma unroll
        for (int u = 0; u < 8; u++) CP_ASYNC16(dstKV[u] + so, srcKV[u] + go);
        CP_COMMIT();
    };

    prefetch(0);

    {
        const size_t qoff = ((size_t)bh * S_ + qt * 128) * HD_;
#pragma unroll
        for (int u = 0; u < 4; u++) {
            int id = u * 256 + tid;
            int row = id >> 3, c8 = (id & 7) * 8;
            *(int4*)(Qs + row * TSTR + c8) =
                *(const int4*)(g_qh + qoff + row * HD_ + c8);
            *(int4*)(Qs + 128 * TSTR + row * TSTR + c8) =
                *(const int4*)(g_ql + qoff + row * HD_ + c8);
        }
    }
    __syncthreads();

    unsigned qh[4][4], ql[4][4];
#pragma unroll
    for (int ks = 0; ks < 4; ks++) {
        unsigned a = su32(Qs + (w * 16 + (lane & 15)) * TSTR + (lane >> 4) * 8 + ks * 16);
        LDSM4(qh[ks][0], qh[ks][1], qh[ks][2], qh[ks][3], a);
        LDSM4(ql[ks][0], ql[ks][1], ql[ks][2], ql[ks][3], a + 128 * TSTR * 2);
    }

    const int qbase = qt * 128 + w * 16;
    const int qg0 = qbase + lr;
    const int qg1 = qg0 + 8;
    const size_t arow0 = ((size_t)bh * S_ + qg0) * S_;
    const size_t arow1 = ((size_t)bh * S_ + qg1) * S_;

    float oacc[8][4];
#pragma unroll
    for (int j = 0; j < 8; j++)
#pragma unroll
        for (int r = 0; r < 4; r++) oacc[j][r] = 0.f;

    float lsum0 = 0.f, lsum1 = 0.f;

    for (int kt = 0; kt < nkt; kt++) {
        CP_WAIT(0);
        __syncthreads();
        if (kt + 1 < nkt) prefetch(kt + 1);

        if (64 * kt <= qbase + 15) {
            const __nv_bfloat16* Ks = Kr + (kt & 1) * KSTAGE;
            const __nv_bfloat16* Vs = Vr + (kt & 1) * KSTAGE;

#pragma unroll
            for (int hh = 0; hh < 2; hh++) {
                float sacc[4][4];
#pragma unroll
                for (int j = 0; j < 4; j++)
#pragma unroll
                    for (int r = 0; r < 4; r++) sacc[j][r] = 0.f;
#pragma unroll
                for (int ks = 0; ks < 4; ks++) {
                    unsigned bhf[4][2], blf[4][2];
#pragma unroll
                    for (int j = 0; j < 4; j++) {
                        unsigned addr = su32(Ks + (hh * 32 + j * 8 + (lane & 7)) * TSTR
                                             + ks * 16 + ((lane >> 3) & 1) * 8);
                        LDSM2(bhf[j][0], bhf[j][1], addr);
                        LDSM2(blf[j][0], blf[j][1], addr + TPLANE_B);
                    }
                    // three passes (spacing 4)
#pragma unroll
                    for (int j = 0; j < 4; j++) MMA16816(sacc[j], qh[ks], bhf[j]);
#pragma unroll
                    for (int j = 0; j < 4; j++) MMA16816(sacc[j], qh[ks], blf[j]);
#pragma unroll
                    for (int j = 0; j < 4; j++) MMA16816(sacc[j], ql[ks], bhf[j]);
                }

                float p[4][4];
#pragma unroll
                for (int j = 0; j < 4; j++) {
                    int kg = kt * 64 + hh * 32 + j * 8 + lc * 2;
                    p[j][0] = (kg     <= qg0) ? __expf(sacc[j][0] * 0.125f) : 0.f;
                    p[j][1] = (kg + 1 <= qg0) ? __expf(sacc[j][1] * 0.125f) : 0.f;
                    p[j][2] = (kg     <= qg1) ? __expf(sacc[j][2] * 0.125f) : 0.f;
                    p[j][3] = (kg + 1 <= qg1) ? __expf(sacc[j][3] * 0.125f) : 0.f;
                    lsum0 += p[j][0] + p[j][1];
                    lsum1 += p[j][2] + p[j][3];
                    *(float2*)(attnP + arow0 + kg) = make_float2(p[j][0], p[j][1]);
                    *(float2*)(attnP + arow1 + kg) = make_float2(p[j][2], p[j][3]);
                }

#pragma unroll
                for (int g = 0; g < 2; g++) {
                    int j0 = 2 * g, j1 = 2 * g + 1;
                    __nv_bfloat16 h00, l00, h01, l01, h02, l02, h03, l03;
                    __nv_bfloat16 h10, l10, h11, l11, h12, l12, h13, l13;
                    f2bf2(p[j0][0], h00, l00); f2bf2(p[j0][1], h01, l01);
                    f2bf2(p[j0][2], h02, l02); f2bf2(p[j0][3], h03, l03);
                    f2bf2(p[j1][0], h10, l10); f2bf2(p[j1][1], h11, l11);
                    f2bf2(p[j1][2], h12, l12); f2bf2(p[j1][3], h13, l13);
                    unsigned aph[4] = { packbf(h00, h01), packbf(h02, h03),
                                        packbf(h10, h11), packbf(h12, h13) };
                    unsigned apl[4] = { packbf(l00, l01), packbf(l02, l03),
                                        packbf(l10, l11), packbf(l12, l13) };

                    // j2 in halves of 4: preload V frags, then 3 passes
#pragma unroll
                    for (int half = 0; half < 2; half++) {
                        unsigned bvh[4][2], bvl[4][2];
#pragma unroll
                        for (int t = 0; t < 4; t++) {
                            int j2 = half * 4 + t;
                            unsigned va = su32(Vs + (hh * 32 + g * 16 + (lane & 15)) * TSTR + j2 * 8);
                            LDSM2T(bvh[t][0], bvh[t][1], va);
                            LDSM2T(bvl[t][0], bvl[t][1], va + TPLANE_B);
                        }
#pragma unroll
                        for (int t = 0; t < 4; t++) MMA16816(oacc[half * 4 + t], aph, bvh[t]);
#pragma unroll
                        for (int t = 0; t < 4; t++) MMA16816(oacc[half * 4 + t], aph, bvl[t]);
#pragma unroll
                        for (int t = 0; t < 4; t++) MMA16816(oacc[half * 4 + t], apl, bvh[t]);
                    }
                }
            }
        }
    }

#pragma unroll
    for (int d = 1; d <= 2; d <<= 1) {
        lsum0 += __shfl_xor_sync(0xffffffffu, lsum0, d);
        lsum1 += __shfl_xor_sync(0xffffffffu, lsum1, d);
    }
    const float rl0 = 1.f / lsum0;
    const float rl1 = 1.f / lsum1;
    if (lc == 0) {
        rlrow[w * 16 + lr]     = rl0;
        rlrow[w * 16 + lr + 8] = rl1;
    }

    {
        const int b = bh >> 4, h = bh & 15;
        const size_t r0 = ((size_t)(b * S_ + qg0)) * D_ + h * HD_;
        const size_t r1 = ((size_t)(b * S_ + qg1)) * D_ + h * HD_;
#pragma unroll
        for (int j2 = 0; j2 < 8; j2++) {
            int cc = j2 * 8 + lc * 2;
            __nv_bfloat16 h0, l0, h1, l1;
            f2bf2(oacc[j2][0] * rl0, h0, l0); f2bf2(oacc[j2][1] * rl0, h1, l1);
            *(__nv_bfloat162*)(g_ah + r0 + cc) = __halves2bfloat162(h0, h1);
            *(__nv_bfloat162*)(g_al + r0 + cc) = __halves2bfloat162(l0, l1);
            f2bf2(oacc[j2][2] * rl1, h0, l0); f2bf2(oacc[j2][3] * rl1, h1, l1);
            *(__nv_bfloat162*)(g_ah + r1 + cc) = __halves2bfloat162(h0, h1);
            *(__nv_bfloat162*)(g_al + r1 + cc) = __halves2bfloat162(l0, l1);
        }
    }

    // fused normalize + zero-fill epilogue (e tiles hot in L2)
    __syncthreads();

    const size_t rowbase = (size_t)bh * S_ + (size_t)qt * 128;
    for (int rr = w; rr < 128; rr += 8) {
        const float rl = rlrow[rr];
        const int kt_last = (qt * 128 + (rr & ~15) + 15) >> 6;
        const int wspan   = (kt_last + 1) << 6;
        float* row = attnP + (rowbase + rr) * S_;
#pragma unroll 4
        for (int c = lane * 4; c < wspan; c += 128) {
            float4 v = *(float4*)(row + c);
            v.x *= rl; v.y *= rl; v.z *= rl; v.w *= rl;
            *(float4*)(row + c) = v;
        }
        const float4 z4 = make_float4(0.f, 0.f, 0.f, 0.f);
#pragma unroll 4
        for (int c = wspan + lane * 4; c < S_; c += 128) {
            *(float4*)(row + c) = z4;
        }
    }
}

// ---------------------------------------------------------------------------
extern "C" void kernel_launch(void* const* d_in, const int* in_sizes, int n_in,
                              void* d_out, int out_size)
{
    long long sz[16];
    int n = (n_in < 16) ? n_in : 16;
    for (int i = 0; i < n; i++) sz[i] = (long long)in_sizes[i];

    int ib = 0;
    for (int i = 1; i < n; i++) if (sz[i] < sz[ib]) ib = i;
    int iq = -1, iw = -1;
    for (int i = 0; i < n; i++)
        for (int j = 0; j < n; j++)
            if (i != j && i != ib && j != ib && sz[i] == 3 * sz[j]) { iq = i; iw = j; }
    int ix = -1;
    for (int i = 0; i < n; i++) {
        if (i == ib || i == iq || i == iw) continue;
        if (sz[i] == 4194304LL || sz[i] == 16777216LL) ix = i;
    }

    const float *x, *W_qkv, *W_out, *b_out;
    if (n_in >= 5 && iq >= 0 && iw >= 0 && ix >= 0) {
        x     = (const float*)d_in[ix];
        W_qkv = (const float*)d_in[iq];
        W_out = (const float*)d_in[iw];
        b_out = (const float*)d_in[ib];
    } else {
        x     = (const float*)d_in[0];
        W_qkv = (const float*)d_in[2];
        W_out = (const float*)d_in[3];
        b_out = (const float*)d_in[4];
    }

    float* ctx_out = (float*)d_out;
    float* attnP   = (float*)d_out + CTX_ELEMS;

    // 0) fp32 -> bf16 hi/lo conversions
    convert_kernel<<<512, 256>>>(x,     MS_ * D_ / 4,     0);
    convert_kernel<<<512, 256>>>(W_qkv, D_ * 3 * D_ / 4,  1);
    convert_kernel<<<512, 256>>>(W_out, D_ * D_ / 4,      2);

    const int gsmem = 3 * STG_B;   // 89,088 B
    cudaFuncSetAttribute(tc_gemm_bf16, cudaFuncAttributeMaxDynamicSharedMemorySize, gsmem);

    // 1) QKV projection -> bf16 hi/lo q,k,v
    {
        dim3 grid(3 * D_ / 64, MS_ / 128);
        tc_gemm_bf16<<<grid, 256, gsmem>>>(nullptr, nullptr, 3 * D_, 1);
    }
    // 2) fused attention + in-kernel normalize/zero
    {
        const int psmem = (2 * 128 * TSTR + 4 * KSTAGE) * 2;   // 110,592 B
        cudaFuncSetAttribute(pv_fused, cudaFuncAttributeMaxDynamicSharedMemorySize, psmem);
        dim3 grid(16, BH_);
        pv_fused<<<grid, 256, psmem>>>(attnP);
    }
    // 3) Output projection + bias
    {
        dim3 grid(D_ / 64, MS_ / 128);
        tc_gemm_bf16<<<grid, 256, gsmem>>>(b_out, ctx_out, D_, 2);
    }
}